// round 13
// baseline (speedup 1.0000x reference)
#include <cuda_runtime.h>
#include <cuda_fp16.h>
#include <cstdint>

// Problem dims (fixed by dataset)
#define M_DIM 8192
#define K_DIM 2048
#define N_DIM 8192

// GEMM tiling: 3 CTAs/SM, 2-stage
#define BM 128
#define BN 128
#define BK 64                 // halves per k-slice = 128 bytes per row
#define NKT (K_DIM / BK)      // 32
#define NSTAGE 2
#define NTHREADS 256
#define A_BYTES (BM * 128)    // 16384
#define B_BYTES (BN * 128)    // 16384
#define STAGE_BYTES (A_BYTES + B_BYTES)            // 32768
#define SMEM_TOTAL (NSTAGE * STAGE_BYTES)          // 65536/CTA (x3 = 192K/SM)

// Scratch (allocation-free rule: __device__ globals)
__device__ __half g_Xh[(size_t)M_DIM * K_DIM];
__device__ __half g_Wq[(size_t)N_DIM * K_DIM];
__device__ float  g_scale[N_DIM];

// ---------------------------------------------------------------------------
__device__ __forceinline__ uint32_t smem_u32(const void* p) {
    return (uint32_t)__cvta_generic_to_shared(p);
}
__device__ __forceinline__ void cp16(uint32_t dst, const void* src) {
    asm volatile("cp.async.cg.shared.global [%0], [%1], 16;\n" :: "r"(dst), "l"(src));
}
__device__ __forceinline__ void ldsm_x4(uint32_t& r0, uint32_t& r1, uint32_t& r2,
                                        uint32_t& r3, uint32_t addr) {
    asm volatile("ldmatrix.sync.aligned.m8n8.x4.shared.b16 {%0,%1,%2,%3}, [%4];"
                 : "=r"(r0), "=r"(r1), "=r"(r2), "=r"(r3) : "r"(addr));
}
__device__ __forceinline__ uint2 pack4_h(float a, float b, float c, float d) {
    __half2 p0 = __floats2half2_rn(a, b);
    __half2 p1 = __floats2half2_rn(c, d);
    uint2 r;
    r.x = *reinterpret_cast<uint32_t*>(&p0);
    r.y = *reinterpret_cast<uint32_t*>(&p1);
    return r;
}

// ---------------------------------------------------------------------------
// Kernel 1 (merged prep):
//   blocks [0, 8192): per-row weight quantization -> ternary fp16 + scale
//   blocks [8192, 8192+8192): x -> fp16, 8 floats per thread
// ---------------------------------------------------------------------------
__global__ __launch_bounds__(256) void prep_kernel(const float* __restrict__ w,
                                                   const float* __restrict__ x) {
    const int tid = threadIdx.x;
    if (blockIdx.x >= N_DIM) {
        size_t i = ((size_t)(blockIdx.x - N_DIM) * 256 + tid) * 2;
        float4 v0 = reinterpret_cast<const float4*>(x)[i];
        float4 v1 = reinterpret_cast<const float4*>(x)[i + 1];
        reinterpret_cast<uint2*>(g_Xh)[i]     = pack4_h(v0.x, v0.y, v0.z, v0.w);
        reinterpret_cast<uint2*>(g_Xh)[i + 1] = pack4_h(v1.x, v1.y, v1.z, v1.w);
        return;
    }

    const int row  = blockIdx.x;
    const int lane = tid & 31, warp = tid >> 5;

    const float4* wr = reinterpret_cast<const float4*>(w + (size_t)row * K_DIM);
    float4 v0 = wr[tid];
    float4 v1 = wr[tid + 256];

    float s = fabsf(v0.x)+fabsf(v0.y)+fabsf(v0.z)+fabsf(v0.w)
            + fabsf(v1.x)+fabsf(v1.y)+fabsf(v1.z)+fabsf(v1.w);
    #pragma unroll
    for (int o = 16; o > 0; o >>= 1) s += __shfl_xor_sync(0xffffffffu, s, o);

    __shared__ float red[8];
    __shared__ float sc_sh;
    if (lane == 0) red[warp] = s;
    __syncthreads();
    if (tid == 0) {
        float tot = 0.f;
        #pragma unroll
        for (int i = 0; i < 8; i++) tot += red[i];
        sc_sh = fmaxf(tot * (1.0f / (float)K_DIM), 1e-5f);
    }
    __syncthreads();
    const float sc = sc_sh;

    float q[8];
    q[0]=__fdiv_rn(v0.x,sc); q[1]=__fdiv_rn(v0.y,sc); q[2]=__fdiv_rn(v0.z,sc); q[3]=__fdiv_rn(v0.w,sc);
    q[4]=__fdiv_rn(v1.x,sc); q[5]=__fdiv_rn(v1.y,sc); q[6]=__fdiv_rn(v1.z,sc); q[7]=__fdiv_rn(v1.w,sc);
    #pragma unroll
    for (int i = 0; i < 8; i++) q[i] = fminf(fmaxf(rintf(q[i]), -1.f), 1.f);

    uint2* dst = reinterpret_cast<uint2*>(g_Wq + (size_t)row * K_DIM);
    dst[tid]       = pack4_h(q[0], q[1], q[2], q[3]);
    dst[tid + 256] = pack4_h(q[4], q[5], q[6], q[7]);

    if (tid == 0) g_scale[row] = sc;
}

// ---------------------------------------------------------------------------
// Kernel 2: fp16 HMMA GEMM.  C[m,n] = scale[n] * sum_k Xh[m,k]*Wq[n,k]
// 128x128x64 tile, 256 thr (8 warps 2x4, warp tile 64x32), 2-stage cp.async,
// 3 CTAs/SM (24 warps/SM), kt-loop unrolled by 2 (compile-time stage slots).
// ---------------------------------------------------------------------------
__global__ __launch_bounds__(NTHREADS, 3) void gemm_f16_kernel(float* __restrict__ C) {
    extern __shared__ char smem[];
    const uint32_t sbase = smem_u32(smem);

    const int tid  = threadIdx.x;
    const int lane = tid & 31;
    const int warp = tid >> 5;
    const int wrow = warp >> 2;           // 0..1 (M, 64 each)
    const int wcol = warp & 3;            // 0..3 (N, 32 each)

    // CTA swizzle: GROUP=8 along M, walk all N inside a group (L2 reuse)
    const int GRID_N = N_DIM / BN;        // 64
    const int GROUP  = 8;
    const int nig    = GROUP * GRID_N;    // 512
    const int bid    = blockIdx.x;
    const int bm     = (bid / nig) * GROUP + (bid % nig) % GROUP;
    const int bn     = (bid % nig) / GROUP;

    const __half* Ag = g_Xh + (size_t)(bm * BM) * K_DIM;
    const __half* Bg = g_Wq + (size_t)(bn * BN) * K_DIM;

    // ldmatrix per-lane row/seg decomposition
    const int a_row = (lane & 7) + ((lane >> 3) & 1) * 8;   // 0..15
    const int a_sh  = lane >> 4;                            // k-seg half 0/1
    const int b_row = (lane & 7) + (lane >> 4) * 8;         // 0..15
    const int b_sh  = (lane >> 3) & 1;
    const int lxor  = lane & 7;

    // Pre-load epilogue scales (hidden under the mainloop)
    const int n_sc = bn * BN + wcol * 32 + 2 * (lane & 3);
    float scv[8];
    #pragma unroll
    for (int nt = 0; nt < 4; nt++) {
        scv[2*nt]   = __ldg(g_scale + n_sc + nt * 8);
        scv[2*nt+1] = __ldg(g_scale + n_sc + nt * 8 + 1);
    }

    float acc[4][4][4];
    #pragma unroll
    for (int a = 0; a < 4; a++)
        #pragma unroll
        for (int b = 0; b < 4; b++)
            #pragma unroll
            for (int c = 0; c < 4; c++) acc[a][b][c] = 0.f;

    // --- stage loader: 8 x 16B per thread (A:4, B:4) ---
    auto load_stage = [&](int kt, uint32_t st) {
        const int kof = kt * BK;
        #pragma unroll
        for (int i = 0; i < 4; i++) {                 // A
            int flat = tid + NTHREADS * i;
            int row = flat >> 3, seg = flat & 7;
            cp16(st + row * 128 + ((seg ^ (row & 7)) << 4),
                 Ag + (size_t)row * K_DIM + kof + seg * 8);
        }
        #pragma unroll
        for (int i = 0; i < 4; i++) {                 // B
            int flat = tid + NTHREADS * i;
            int row = flat >> 3, seg = flat & 7;
            cp16(st + A_BYTES + row * 128 + ((seg ^ (row & 7)) << 4),
                 Bg + (size_t)row * K_DIM + kof + seg * 8);
        }
        asm volatile("cp.async.commit_group;\n" ::: "memory");
    };

    // one k-iteration with compile-time stage slots
    auto iter = [&](int kt, uint32_t cslot, uint32_t lslot) {
        asm volatile("cp.async.wait_group 0;\n" ::: "memory");  // stage kt resident
        __syncthreads();                                        // slot of kt-1 free
        const int j = kt + NSTAGE - 1;
        if (j < NKT) load_stage(j, sbase + lslot * STAGE_BYTES); // overlaps compute
        const uint32_t aB = sbase + cslot * STAGE_BYTES;
        const uint32_t bB = aB + A_BYTES;
        #pragma unroll
        for (int ks = 0; ks < 4; ks++) {
            uint32_t af[4][4], bf[2][4];
            #pragma unroll
            for (int mt = 0; mt < 4; mt++) {
                const int row = wrow * 64 + mt * 16 + a_row;
                const int seg = 2 * ks + a_sh;
                ldsm_x4(af[mt][0], af[mt][1], af[mt][2], af[mt][3],
                        aB + row * 128 + ((seg ^ lxor) << 4));
            }
            #pragma unroll
            for (int nt = 0; nt < 2; nt++) {
                const int row = wcol * 32 + nt * 16 + b_row;
                const int seg = 2 * ks + b_sh;
                ldsm_x4(bf[nt][0], bf[nt][1], bf[nt][2], bf[nt][3],
                        bB + row * 128 + ((seg ^ lxor) << 4));
            }
            #pragma unroll
            for (int mt = 0; mt < 4; mt++)
                #pragma unroll
                for (int nt = 0; nt < 2; nt++) {
                    asm volatile(
                        "mma.sync.aligned.m16n8k16.row.col.f32.f16.f16.f32 "
                        "{%0,%1,%2,%3}, {%4,%5,%6,%7}, {%8,%9}, {%0,%1,%2,%3};\n"
                        : "+f"(acc[mt][2*nt][0]), "+f"(acc[mt][2*nt][1]),
                          "+f"(acc[mt][2*nt][2]), "+f"(acc[mt][2*nt][3])
                        : "r"(af[mt][0]), "r"(af[mt][1]), "r"(af[mt][2]), "r"(af[mt][3]),
                          "r"(bf[nt][0]), "r"(bf[nt][1]));
                    asm volatile(
                        "mma.sync.aligned.m16n8k16.row.col.f32.f16.f16.f32 "
                        "{%0,%1,%2,%3}, {%4,%5,%6,%7}, {%8,%9}, {%0,%1,%2,%3};\n"
                        : "+f"(acc[mt][2*nt+1][0]), "+f"(acc[mt][2*nt+1][1]),
                          "+f"(acc[mt][2*nt+1][2]), "+f"(acc[mt][2*nt+1][3])
                        : "r"(af[mt][0]), "r"(af[mt][1]), "r"(af[mt][2]), "r"(af[mt][3]),
                          "r"(bf[nt][2]), "r"(bf[nt][3]));
                }
        }
    };

    // prologue: stage 0
    load_stage(0, sbase);

    // main loop: 32 iterations unrolled by 2 (stage slots constant)
    #pragma unroll 1
    for (int kt = 0; kt < NKT; kt += 2) {
        iter(kt + 0, 0, 1);
        iter(kt + 1, 1, 0);
    }

    // ---- epilogue: per-column scale (pre-loaded), fp32 stores ----
    const int l4r = lane >> 2;            // 0..7
    #pragma unroll
    for (int mt = 0; mt < 4; mt++) {
        const int r0 = bm * BM + wrow * 64 + mt * 16 + l4r;
        #pragma unroll
        for (int nt = 0; nt < 4; nt++) {
            const int n0 = n_sc + nt * 8;
            float2 v0 = make_float2(acc[mt][nt][0] * scv[2*nt], acc[mt][nt][1] * scv[2*nt+1]);
            float2 v1 = make_float2(acc[mt][nt][2] * scv[2*nt], acc[mt][nt][3] * scv[2*nt+1]);
            *reinterpret_cast<float2*>(C + (size_t)r0 * N_DIM + n0)       = v0;
            *reinterpret_cast<float2*>(C + (size_t)(r0 + 8) * N_DIM + n0) = v1;
        }
    }
}

// ---------------------------------------------------------------------------
extern "C" void kernel_launch(void* const* d_in, const int* in_sizes, int n_in,
                              void* d_out, int out_size) {
    (void)in_sizes; (void)n_in; (void)out_size;
    const float* x = (const float*)d_in[0];
    const float* w = (const float*)d_in[1];
    float* out = (float*)d_out;

    // merged prep: 8192 W-row blocks + 8192 x-conversion blocks (8 floats/thr)
    prep_kernel<<<N_DIM + (unsigned)((size_t)M_DIM * K_DIM / 8 / 256), 256>>>(w, x);

    cudaFuncSetAttribute(gemm_f16_kernel,
                         cudaFuncAttributeMaxDynamicSharedMemorySize, SMEM_TOTAL);
    gemm_f16_kernel<<<(M_DIM / BM) * (N_DIM / BN), NTHREADS, SMEM_TOTAL>>>(out);
}

// round 14
// speedup vs baseline: 2.8282x; 2.8282x over previous
#include <cuda_runtime.h>
#include <cuda_fp16.h>
#include <cstdint>

// Problem dims (fixed by dataset)
#define M_DIM 8192
#define K_DIM 2048
#define N_DIM 8192

// GEMM tiling: 2 CTAs/SM (RF-exact config: 2 x 256thr x 128regs = 64K RF)
#define BM 128
#define BN 128
#define BK 64                 // halves per k-slice = 128 bytes per row
#define NKT (K_DIM / BK)      // 32
#define NSTAGE 3
#define NTHREADS 256
#define A_BYTES (BM * 128)    // 16384
#define B_BYTES (BN * 128)    // 16384
#define STAGE_BYTES (A_BYTES + B_BYTES)            // 32768
#define SMEM_TOTAL (NSTAGE * STAGE_BYTES)          // 98304/CTA (x2 = 192K/SM)

// Scratch (allocation-free rule: __device__ globals)
__device__ __half g_Xh[(size_t)M_DIM * K_DIM];
__device__ __half g_Wq[(size_t)N_DIM * K_DIM];
__device__ float  g_scale[N_DIM];

// ---------------------------------------------------------------------------
__device__ __forceinline__ uint32_t smem_u32(const void* p) {
    return (uint32_t)__cvta_generic_to_shared(p);
}
__device__ __forceinline__ void cp16_cg(uint32_t dst, const void* src) {
    asm volatile("cp.async.cg.shared.global [%0], [%1], 16;\n" :: "r"(dst), "l"(src));
}
// L1-allocating variant: co-resident CTA shares the same B panel -> L1 hits
__device__ __forceinline__ void cp16_ca(uint32_t dst, const void* src) {
    asm volatile("cp.async.ca.shared.global [%0], [%1], 16;\n" :: "r"(dst), "l"(src));
}
__device__ __forceinline__ void ldsm_x4(uint32_t& r0, uint32_t& r1, uint32_t& r2,
                                        uint32_t& r3, uint32_t addr) {
    asm volatile("ldmatrix.sync.aligned.m8n8.x4.shared.b16 {%0,%1,%2,%3}, [%4];"
                 : "=r"(r0), "=r"(r1), "=r"(r2), "=r"(r3) : "r"(addr));
}
__device__ __forceinline__ uint2 pack4_h(float a, float b, float c, float d) {
    __half2 p0 = __floats2half2_rn(a, b);
    __half2 p1 = __floats2half2_rn(c, d);
    uint2 r;
    r.x = *reinterpret_cast<uint32_t*>(&p0);
    r.y = *reinterpret_cast<uint32_t*>(&p1);
    return r;
}

// ---------------------------------------------------------------------------
// Kernel 1 (merged prep):
//   blocks [0, 8192): per-row weight quantization -> ternary fp16 + scale
//   blocks [8192, 8192+8192): x -> fp16, 8 floats per thread
// ---------------------------------------------------------------------------
__global__ __launch_bounds__(256) void prep_kernel(const float* __restrict__ w,
                                                   const float* __restrict__ x) {
    const int tid = threadIdx.x;
    if (blockIdx.x >= N_DIM) {
        size_t i = ((size_t)(blockIdx.x - N_DIM) * 256 + tid) * 2;
        float4 v0 = reinterpret_cast<const float4*>(x)[i];
        float4 v1 = reinterpret_cast<const float4*>(x)[i + 1];
        reinterpret_cast<uint2*>(g_Xh)[i]     = pack4_h(v0.x, v0.y, v0.z, v0.w);
        reinterpret_cast<uint2*>(g_Xh)[i + 1] = pack4_h(v1.x, v1.y, v1.z, v1.w);
        return;
    }

    const int row  = blockIdx.x;
    const int lane = tid & 31, warp = tid >> 5;

    const float4* wr = reinterpret_cast<const float4*>(w + (size_t)row * K_DIM);
    float4 v0 = wr[tid];
    float4 v1 = wr[tid + 256];

    float s = fabsf(v0.x)+fabsf(v0.y)+fabsf(v0.z)+fabsf(v0.w)
            + fabsf(v1.x)+fabsf(v1.y)+fabsf(v1.z)+fabsf(v1.w);
    #pragma unroll
    for (int o = 16; o > 0; o >>= 1) s += __shfl_xor_sync(0xffffffffu, s, o);

    __shared__ float red[8];
    __shared__ float sc_sh;
    if (lane == 0) red[warp] = s;
    __syncthreads();
    if (tid == 0) {
        float tot = 0.f;
        #pragma unroll
        for (int i = 0; i < 8; i++) tot += red[i];
        sc_sh = fmaxf(tot * (1.0f / (float)K_DIM), 1e-5f);
    }
    __syncthreads();
    const float sc = sc_sh;

    float q[8];
    q[0]=__fdiv_rn(v0.x,sc); q[1]=__fdiv_rn(v0.y,sc); q[2]=__fdiv_rn(v0.z,sc); q[3]=__fdiv_rn(v0.w,sc);
    q[4]=__fdiv_rn(v1.x,sc); q[5]=__fdiv_rn(v1.y,sc); q[6]=__fdiv_rn(v1.z,sc); q[7]=__fdiv_rn(v1.w,sc);
    #pragma unroll
    for (int i = 0; i < 8; i++) q[i] = fminf(fmaxf(rintf(q[i]), -1.f), 1.f);

    uint2* dst = reinterpret_cast<uint2*>(g_Wq + (size_t)row * K_DIM);
    dst[tid]       = pack4_h(q[0], q[1], q[2], q[3]);
    dst[tid + 256] = pack4_h(q[4], q[5], q[6], q[7]);

    if (tid == 0) g_scale[row] = sc;
}

// ---------------------------------------------------------------------------
// Kernel 2: fp16 HMMA GEMM.  C[m,n] = scale[n] * sum_k Xh[m,k]*Wq[n,k]
// 128x128x64 tile, 256 thr (8 warps 2x4, warp tile 64x32), 3-stage cp.async,
// 2 CTAs/SM, kt-loop unrolled by 3 (compile-time stage slots), B via .ca.
// ---------------------------------------------------------------------------
__global__ __launch_bounds__(NTHREADS, 2) void gemm_f16_kernel(float* __restrict__ C) {
    extern __shared__ char smem[];
    const uint32_t sbase = smem_u32(smem);

    const int tid  = threadIdx.x;
    const int lane = tid & 31;
    const int warp = tid >> 5;
    const int wrow = warp >> 2;           // 0..1 (M, 64 each)
    const int wcol = warp & 3;            // 0..3 (N, 32 each)

    // CTA swizzle: GROUP=8 along M, walk all N inside a group (L2 reuse);
    // adjacent bids share bn -> co-resident CTAs reuse the same B panel.
    const int GRID_N = N_DIM / BN;        // 64
    const int GROUP  = 8;
    const int nig    = GROUP * GRID_N;    // 512
    const int bid    = blockIdx.x;
    const int bm     = (bid / nig) * GROUP + (bid % nig) % GROUP;
    const int bn     = (bid % nig) / GROUP;

    const __half* Ag = g_Xh + (size_t)(bm * BM) * K_DIM;
    const __half* Bg = g_Wq + (size_t)(bn * BN) * K_DIM;

    // ldmatrix per-lane row/seg decomposition
    const int a_row = (lane & 7) + ((lane >> 3) & 1) * 8;   // 0..15
    const int a_sh  = lane >> 4;                            // k-seg half 0/1
    const int b_row = (lane & 7) + (lane >> 4) * 8;         // 0..15
    const int b_sh  = (lane >> 3) & 1;
    const int lxor  = lane & 7;

    // Pre-load epilogue scales (hidden under the mainloop)
    const int n_sc = bn * BN + wcol * 32 + 2 * (lane & 3);
    float scv[8];
    #pragma unroll
    for (int nt = 0; nt < 4; nt++) {
        scv[2*nt]   = __ldg(g_scale + n_sc + nt * 8);
        scv[2*nt+1] = __ldg(g_scale + n_sc + nt * 8 + 1);
    }

    float acc[4][4][4];
    #pragma unroll
    for (int a = 0; a < 4; a++)
        #pragma unroll
        for (int b = 0; b < 4; b++)
            #pragma unroll
            for (int c = 0; c < 4; c++) acc[a][b][c] = 0.f;

    // --- stage loader: 8 x 16B per thread (A:4 .cg, B:4 .ca) ---
    auto load_stage = [&](int kt, uint32_t st) {
        const int kof = kt * BK;
        #pragma unroll
        for (int i = 0; i < 4; i++) {                 // A (private per CTA pair)
            int flat = tid + NTHREADS * i;
            int row = flat >> 3, seg = flat & 7;
            cp16_cg(st + row * 128 + ((seg ^ (row & 7)) << 4),
                    Ag + (size_t)row * K_DIM + kof + seg * 8);
        }
        #pragma unroll
        for (int i = 0; i < 4; i++) {                 // B (shared with co-resident CTA)
            int flat = tid + NTHREADS * i;
            int row = flat >> 3, seg = flat & 7;
            cp16_ca(st + A_BYTES + row * 128 + ((seg ^ (row & 7)) << 4),
                    Bg + (size_t)row * K_DIM + kof + seg * 8);
        }
        asm volatile("cp.async.commit_group;\n" ::: "memory");
    };

    // one k-iteration with compile-time stage slots
    auto iter = [&](int kt, uint32_t cslot, uint32_t lslot) {
        asm volatile("cp.async.wait_group %0;\n" :: "n"(NSTAGE - 2) : "memory");
        __syncthreads();
        const int j = kt + NSTAGE - 1;
        if (j < NKT) {
            load_stage(j, sbase + lslot * STAGE_BYTES);
        } else {
            asm volatile("cp.async.commit_group;\n" ::: "memory");
        }
        const uint32_t aB = sbase + cslot * STAGE_BYTES;
        const uint32_t bB = aB + A_BYTES;
        #pragma unroll
        for (int ks = 0; ks < 4; ks++) {
            uint32_t af[4][4], bf[2][4];
            #pragma unroll
            for (int mt = 0; mt < 4; mt++) {
                const int row = wrow * 64 + mt * 16 + a_row;
                const int seg = 2 * ks + a_sh;
                ldsm_x4(af[mt][0], af[mt][1], af[mt][2], af[mt][3],
                        aB + row * 128 + ((seg ^ lxor) << 4));
            }
            #pragma unroll
            for (int nt = 0; nt < 2; nt++) {
                const int row = wcol * 32 + nt * 16 + b_row;
                const int seg = 2 * ks + b_sh;
                ldsm_x4(bf[nt][0], bf[nt][1], bf[nt][2], bf[nt][3],
                        bB + row * 128 + ((seg ^ lxor) << 4));
            }
            #pragma unroll
            for (int mt = 0; mt < 4; mt++)
                #pragma unroll
                for (int nt = 0; nt < 2; nt++) {
                    asm volatile(
                        "mma.sync.aligned.m16n8k16.row.col.f32.f16.f16.f32 "
                        "{%0,%1,%2,%3}, {%4,%5,%6,%7}, {%8,%9}, {%0,%1,%2,%3};\n"
                        : "+f"(acc[mt][2*nt][0]), "+f"(acc[mt][2*nt][1]),
                          "+f"(acc[mt][2*nt][2]), "+f"(acc[mt][2*nt][3])
                        : "r"(af[mt][0]), "r"(af[mt][1]), "r"(af[mt][2]), "r"(af[mt][3]),
                          "r"(bf[nt][0]), "r"(bf[nt][1]));
                    asm volatile(
                        "mma.sync.aligned.m16n8k16.row.col.f32.f16.f16.f32 "
                        "{%0,%1,%2,%3}, {%4,%5,%6,%7}, {%8,%9}, {%0,%1,%2,%3};\n"
                        : "+f"(acc[mt][2*nt+1][0]), "+f"(acc[mt][2*nt+1][1]),
                          "+f"(acc[mt][2*nt+1][2]), "+f"(acc[mt][2*nt+1][3])
                        : "r"(af[mt][0]), "r"(af[mt][1]), "r"(af[mt][2]), "r"(af[mt][3]),
                          "r"(bf[nt][2]), "r"(bf[nt][3]));
                }
        }
    };

    // prologue: stages 0,1
    load_stage(0, sbase);
    load_stage(1, sbase + STAGE_BYTES);

    // main loop: 30 iterations unrolled by 3 (stage slots constant), + 2 tail
    #pragma unroll 1
    for (int kt = 0; kt < 30; kt += 3) {
        iter(kt + 0, 0, 2);
        iter(kt + 1, 1, 0);
        iter(kt + 2, 2, 1);
    }
    iter(30, 0, 2);
    iter(31, 1, 0);

    // ---- epilogue: per-column scale (pre-loaded), fp32 stores ----
    const int l4r = lane >> 2;            // 0..7
    #pragma unroll
    for (int mt = 0; mt < 4; mt++) {
        const int r0 = bm * BM + wrow * 64 + mt * 16 + l4r;
        #pragma unroll
        for (int nt = 0; nt < 4; nt++) {
            const int n0 = n_sc + nt * 8;
            float2 v0 = make_float2(acc[mt][nt][0] * scv[2*nt], acc[mt][nt][1] * scv[2*nt+1]);
            float2 v1 = make_float2(acc[mt][nt][2] * scv[2*nt], acc[mt][nt][3] * scv[2*nt+1]);
            *reinterpret_cast<float2*>(C + (size_t)r0 * N_DIM + n0)       = v0;
            *reinterpret_cast<float2*>(C + (size_t)(r0 + 8) * N_DIM + n0) = v1;
        }
    }
}

// ---------------------------------------------------------------------------
extern "C" void kernel_launch(void* const* d_in, const int* in_sizes, int n_in,
                              void* d_out, int out_size) {
    (void)in_sizes; (void)n_in; (void)out_size;
    const float* x = (const float*)d_in[0];
    const float* w = (const float*)d_in[1];
    float* out = (float*)d_out;

    // merged prep: 8192 W-row blocks + 8192 x-conversion blocks (8 floats/thr)
    prep_kernel<<<N_DIM + (unsigned)((size_t)M_DIM * K_DIM / 8 / 256), 256>>>(w, x);

    cudaFuncSetAttribute(gemm_f16_kernel,
                         cudaFuncAttributeMaxDynamicSharedMemorySize, SMEM_TOTAL);
    gemm_f16_kernel<<<(M_DIM / BM) * (N_DIM / BN), NTHREADS, SMEM_TOTAL>>>(out);
}

// round 15
// speedup vs baseline: 3.0014x; 1.0612x over previous
#include <cuda_runtime.h>
#include <cuda_fp16.h>
#include <cstdint>

// Problem dims (fixed by dataset)
#define M_DIM 8192
#define K_DIM 2048
#define N_DIM 8192

// GEMM tiling: 2 CTAs/SM (RF-exact: 2 x 256thr x 128regs = 64K RF/SM)
#define BM 128
#define BN 128
#define BK 64                 // halves per k-slice = 128 bytes per row
#define NKT (K_DIM / BK)      // 32
#define NSTAGE 3
#define NTHREADS 256
#define A_BYTES (BM * 128)    // 16384
#define B_BYTES (BN * 128)    // 16384
#define STAGE_BYTES (A_BYTES + B_BYTES)            // 32768
#define SMEM_TOTAL (NSTAGE * STAGE_BYTES)          // 98304/CTA (x2 = 192K/SM)

// Scratch (allocation-free rule: __device__ globals)
__device__ __half g_Xh[(size_t)M_DIM * K_DIM];
__device__ __half g_Wq[(size_t)N_DIM * K_DIM];
__device__ float  g_scale[N_DIM];

// ---------------------------------------------------------------------------
__device__ __forceinline__ uint32_t smem_u32(const void* p) {
    return (uint32_t)__cvta_generic_to_shared(p);
}
__device__ __forceinline__ void cp16(uint32_t dst, const void* src) {
    asm volatile("cp.async.cg.shared.global [%0], [%1], 16;\n" :: "r"(dst), "l"(src));
}
__device__ __forceinline__ void ldsm_x4(uint32_t& r0, uint32_t& r1, uint32_t& r2,
                                        uint32_t& r3, uint32_t addr) {
    asm volatile("ldmatrix.sync.aligned.m8n8.x4.shared.b16 {%0,%1,%2,%3}, [%4];"
                 : "=r"(r0), "=r"(r1), "=r"(r2), "=r"(r3) : "r"(addr));
}
__device__ __forceinline__ uint2 pack4_h(float a, float b, float c, float d) {
    __half2 p0 = __floats2half2_rn(a, b);
    __half2 p1 = __floats2half2_rn(c, d);
    uint2 r;
    r.x = *reinterpret_cast<uint32_t*>(&p0);
    r.y = *reinterpret_cast<uint32_t*>(&p1);
    return r;
}

// ---------------------------------------------------------------------------
// Kernel 1 (merged prep):
//   blocks [0, 8192): per-row weight quantization -> ternary fp16 + scale
//   blocks [8192, 8192+8192): x -> fp16, 8 floats per thread
// ---------------------------------------------------------------------------
__global__ __launch_bounds__(256) void prep_kernel(const float* __restrict__ w,
                                                   const float* __restrict__ x) {
    const int tid = threadIdx.x;
    if (blockIdx.x >= N_DIM) {
        size_t i = ((size_t)(blockIdx.x - N_DIM) * 256 + tid) * 2;
        float4 v0 = reinterpret_cast<const float4*>(x)[i];
        float4 v1 = reinterpret_cast<const float4*>(x)[i + 1];
        reinterpret_cast<uint2*>(g_Xh)[i]     = pack4_h(v0.x, v0.y, v0.z, v0.w);
        reinterpret_cast<uint2*>(g_Xh)[i + 1] = pack4_h(v1.x, v1.y, v1.z, v1.w);
        return;
    }

    const int row  = blockIdx.x;
    const int lane = tid & 31, warp = tid >> 5;

    const float4* wr = reinterpret_cast<const float4*>(w + (size_t)row * K_DIM);
    float4 v0 = wr[tid];
    float4 v1 = wr[tid + 256];

    float s = fabsf(v0.x)+fabsf(v0.y)+fabsf(v0.z)+fabsf(v0.w)
            + fabsf(v1.x)+fabsf(v1.y)+fabsf(v1.z)+fabsf(v1.w);
    #pragma unroll
    for (int o = 16; o > 0; o >>= 1) s += __shfl_xor_sync(0xffffffffu, s, o);

    __shared__ float red[8];
    __shared__ float sc_sh;
    if (lane == 0) red[warp] = s;
    __syncthreads();
    if (tid == 0) {
        float tot = 0.f;
        #pragma unroll
        for (int i = 0; i < 8; i++) tot += red[i];
        sc_sh = fmaxf(tot * (1.0f / (float)K_DIM), 1e-5f);
    }
    __syncthreads();
    const float sc = sc_sh;

    float q[8];
    q[0]=__fdiv_rn(v0.x,sc); q[1]=__fdiv_rn(v0.y,sc); q[2]=__fdiv_rn(v0.z,sc); q[3]=__fdiv_rn(v0.w,sc);
    q[4]=__fdiv_rn(v1.x,sc); q[5]=__fdiv_rn(v1.y,sc); q[6]=__fdiv_rn(v1.z,sc); q[7]=__fdiv_rn(v1.w,sc);
    #pragma unroll
    for (int i = 0; i < 8; i++) q[i] = fminf(fmaxf(rintf(q[i]), -1.f), 1.f);

    uint2* dst = reinterpret_cast<uint2*>(g_Wq + (size_t)row * K_DIM);
    dst[tid]       = pack4_h(q[0], q[1], q[2], q[3]);
    dst[tid + 256] = pack4_h(q[4], q[5], q[6], q[7]);

    if (tid == 0) g_scale[row] = sc;
}

// ---------------------------------------------------------------------------
// Kernel 2: fp16 HMMA GEMM.  C[m,n] = scale[n] * sum_k Xh[m,k]*Wq[n,k]
// 128x128x64 tile, 256 thr (8 warps 2x4, warp tile 64x32), 3-stage cp.async,
// 2 CTAs/SM, kt-loop unrolled by 3 (compile-time stage slots).  [R11 config]
// ---------------------------------------------------------------------------
__global__ __launch_bounds__(NTHREADS, 2) void gemm_f16_kernel(float* __restrict__ C) {
    extern __shared__ char smem[];
    const uint32_t sbase = smem_u32(smem);

    const int tid  = threadIdx.x;
    const int lane = tid & 31;
    const int warp = tid >> 5;
    const int wrow = warp >> 2;           // 0..1 (M, 64 each)
    const int wcol = warp & 3;            // 0..3 (N, 32 each)

    // CTA swizzle: GROUP=8 along M, walk all N inside a group (L2 reuse)
    const int GRID_N = N_DIM / BN;        // 64
    const int GROUP  = 8;
    const int nig    = GROUP * GRID_N;    // 512
    const int bid    = blockIdx.x;
    const int bm     = (bid / nig) * GROUP + (bid % nig) % GROUP;
    const int bn     = (bid % nig) / GROUP;

    const __half* Ag = g_Xh + (size_t)(bm * BM) * K_DIM;
    const __half* Bg = g_Wq + (size_t)(bn * BN) * K_DIM;

    // ldmatrix per-lane row/seg decomposition
    const int a_row = (lane & 7) + ((lane >> 3) & 1) * 8;   // 0..15
    const int a_sh  = lane >> 4;                            // k-seg half 0/1
    const int b_row = (lane & 7) + (lane >> 4) * 8;         // 0..15
    const int b_sh  = (lane >> 3) & 1;
    const int lxor  = lane & 7;

    // Pre-load epilogue scales (hidden under the mainloop)
    const int n_sc = bn * BN + wcol * 32 + 2 * (lane & 3);
    float scv[8];
    #pragma unroll
    for (int nt = 0; nt < 4; nt++) {
        scv[2*nt]   = __ldg(g_scale + n_sc + nt * 8);
        scv[2*nt+1] = __ldg(g_scale + n_sc + nt * 8 + 1);
    }

    float acc[4][4][4];
    #pragma unroll
    for (int a = 0; a < 4; a++)
        #pragma unroll
        for (int b = 0; b < 4; b++)
            #pragma unroll
            for (int c = 0; c < 4; c++) acc[a][b][c] = 0.f;

    // --- stage loader: 8 x 16B per thread (A:4, B:4) ---
    auto load_stage = [&](int kt, uint32_t st) {
        const int kof = kt * BK;
        #pragma unroll
        for (int i = 0; i < 4; i++) {                 // A
            int flat = tid + NTHREADS * i;
            int row = flat >> 3, seg = flat & 7;
            cp16(st + row * 128 + ((seg ^ (row & 7)) << 4),
                 Ag + (size_t)row * K_DIM + kof + seg * 8);
        }
        #pragma unroll
        for (int i = 0; i < 4; i++) {                 // B
            int flat = tid + NTHREADS * i;
            int row = flat >> 3, seg = flat & 7;
            cp16(st + A_BYTES + row * 128 + ((seg ^ (row & 7)) << 4),
                 Bg + (size_t)row * K_DIM + kof + seg * 8);
        }
        asm volatile("cp.async.commit_group;\n" ::: "memory");
    };

    // one k-iteration with compile-time stage slots
    auto iter = [&](int kt, uint32_t cslot, uint32_t lslot) {
        asm volatile("cp.async.wait_group %0;\n" :: "n"(NSTAGE - 2) : "memory");
        __syncthreads();
        const int j = kt + NSTAGE - 1;
        if (j < NKT) {
            load_stage(j, sbase + lslot * STAGE_BYTES);
        } else {
            asm volatile("cp.async.commit_group;\n" ::: "memory");
        }
        const uint32_t aB = sbase + cslot * STAGE_BYTES;
        const uint32_t bB = aB + A_BYTES;
        #pragma unroll
        for (int ks = 0; ks < 4; ks++) {
            uint32_t af[4][4], bf[2][4];
            #pragma unroll
            for (int mt = 0; mt < 4; mt++) {
                const int row = wrow * 64 + mt * 16 + a_row;
                const int seg = 2 * ks + a_sh;
                ldsm_x4(af[mt][0], af[mt][1], af[mt][2], af[mt][3],
                        aB + row * 128 + ((seg ^ lxor) << 4));
            }
            #pragma unroll
            for (int nt = 0; nt < 2; nt++) {
                const int row = wcol * 32 + nt * 16 + b_row;
                const int seg = 2 * ks + b_sh;
                ldsm_x4(bf[nt][0], bf[nt][1], bf[nt][2], bf[nt][3],
                        bB + row * 128 + ((seg ^ lxor) << 4));
            }
            #pragma unroll
            for (int mt = 0; mt < 4; mt++)
                #pragma unroll
                for (int nt = 0; nt < 2; nt++) {
                    asm volatile(
                        "mma.sync.aligned.m16n8k16.row.col.f32.f16.f16.f32 "
                        "{%0,%1,%2,%3}, {%4,%5,%6,%7}, {%8,%9}, {%0,%1,%2,%3};\n"
                        : "+f"(acc[mt][2*nt][0]), "+f"(acc[mt][2*nt][1]),
                          "+f"(acc[mt][2*nt][2]), "+f"(acc[mt][2*nt][3])
                        : "r"(af[mt][0]), "r"(af[mt][1]), "r"(af[mt][2]), "r"(af[mt][3]),
                          "r"(bf[nt][0]), "r"(bf[nt][1]));
                    asm volatile(
                        "mma.sync.aligned.m16n8k16.row.col.f32.f16.f16.f32 "
                        "{%0,%1,%2,%3}, {%4,%5,%6,%7}, {%8,%9}, {%0,%1,%2,%3};\n"
                        : "+f"(acc[mt][2*nt+1][0]), "+f"(acc[mt][2*nt+1][1]),
                          "+f"(acc[mt][2*nt+1][2]), "+f"(acc[mt][2*nt+1][3])
                        : "r"(af[mt][0]), "r"(af[mt][1]), "r"(af[mt][2]), "r"(af[mt][3]),
                          "r"(bf[nt][2]), "r"(bf[nt][3]));
                }
        }
    };

    // prologue: stages 0,1
    load_stage(0, sbase);
    load_stage(1, sbase + STAGE_BYTES);

    // main loop: 30 iterations unrolled by 3 (stage slots constant), + 2 tail
    #pragma unroll 1
    for (int kt = 0; kt < 30; kt += 3) {
        iter(kt + 0, 0, 2);
        iter(kt + 1, 1, 0);
        iter(kt + 2, 2, 1);
    }
    iter(30, 0, 2);
    iter(31, 1, 0);

    // ---- epilogue: per-column scale (pre-loaded), fp32 stores ----
    const int l4r = lane >> 2;            // 0..7
    #pragma unroll
    for (int mt = 0; mt < 4; mt++) {
        const int r0 = bm * BM + wrow * 64 + mt * 16 + l4r;
        #pragma unroll
        for (int nt = 0; nt < 4; nt++) {
            const int n0 = n_sc + nt * 8;
            float2 v0 = make_float2(acc[mt][nt][0] * scv[2*nt], acc[mt][nt][1] * scv[2*nt+1]);
            float2 v1 = make_float2(acc[mt][nt][2] * scv[2*nt], acc[mt][nt][3] * scv[2*nt+1]);
            *reinterpret_cast<float2*>(C + (size_t)r0 * N_DIM + n0)       = v0;
            *reinterpret_cast<float2*>(C + (size_t)(r0 + 8) * N_DIM + n0) = v1;
        }
    }
}

// ---------------------------------------------------------------------------
extern "C" void kernel_launch(void* const* d_in, const int* in_sizes, int n_in,
                              void* d_out, int out_size) {
    (void)in_sizes; (void)n_in; (void)out_size;
    const float* x = (const float*)d_in[0];
    const float* w = (const float*)d_in[1];
    float* out = (float*)d_out;

    // merged prep: 8192 W-row blocks + 8192 x-conversion blocks (8 floats/thr)
    prep_kernel<<<N_DIM + (unsigned)((size_t)M_DIM * K_DIM / 8 / 256), 256>>>(w, x);

    cudaFuncSetAttribute(gemm_f16_kernel,
                         cudaFuncAttributeMaxDynamicSharedMemorySize, SMEM_TOTAL);
    gemm_f16_kernel<<<(M_DIM / BM) * (N_DIM / BN), NTHREADS, SMEM_TOTAL>>>(out);
}

// round 17
// speedup vs baseline: 3.0136x; 1.0041x over previous
#include <cuda_runtime.h>
#include <cuda_fp16.h>
#include <cstdint>

// Problem dims (fixed by dataset)
#define M_DIM 8192
#define K_DIM 2048
#define N_DIM 8192

// GEMM tiling: 2 CTAs/SM (RF-exact: 2 x 256thr x 128regs = 64K RF/SM)
#define BM 128
#define BN 128
#define BK 64                 // halves per k-slice = 128 bytes per row
#define NKT (K_DIM / BK)      // 32
#define NSTAGE 3
#define NTHREADS 256
#define A_BYTES (BM * 128)    // 16384
#define B_BYTES (BN * 128)    // 16384
#define STAGE_BYTES (A_BYTES + B_BYTES)            // 32768
#define SMEM_TOTAL (NSTAGE * STAGE_BYTES)          // 98304/CTA (x2 = 192K/SM)

// Scratch (allocation-free rule: __device__ globals)
__device__ __half g_Xh[(size_t)M_DIM * K_DIM];
__device__ __half g_Wq[(size_t)N_DIM * K_DIM];
__device__ float  g_scale[N_DIM];

// ---------------------------------------------------------------------------
__device__ __forceinline__ uint32_t smem_u32(const void* p) {
    return (uint32_t)__cvta_generic_to_shared(p);
}
__device__ __forceinline__ void cp16(uint32_t dst, const void* src) {
    asm volatile("cp.async.cg.shared.global [%0], [%1], 16;\n" :: "r"(dst), "l"(src));
}
__device__ __forceinline__ void ldsm_x4(uint32_t& r0, uint32_t& r1, uint32_t& r2,
                                        uint32_t& r3, uint32_t addr) {
    asm volatile("ldmatrix.sync.aligned.m8n8.x4.shared.b16 {%0,%1,%2,%3}, [%4];"
                 : "=r"(r0), "=r"(r1), "=r"(r2), "=r"(r3) : "r"(addr));
}
__device__ __forceinline__ uint2 pack4_h(float a, float b, float c, float d) {
    __half2 p0 = __floats2half2_rn(a, b);
    __half2 p1 = __floats2half2_rn(c, d);
    uint2 r;
    r.x = *reinterpret_cast<uint32_t*>(&p0);
    r.y = *reinterpret_cast<uint32_t*>(&p1);
    return r;
}

// ---------------------------------------------------------------------------
// Kernel 1 (merged prep):
//   blocks [0, 8192): per-row weight quantization -> ternary fp16 + scale
//   blocks [8192, 8192+8192): x -> fp16, 8 floats per thread
// ---------------------------------------------------------------------------
__global__ __launch_bounds__(256) void prep_kernel(const float* __restrict__ w,
                                                   const float* __restrict__ x) {
    const int tid = threadIdx.x;
    if (blockIdx.x >= N_DIM) {
        size_t i = ((size_t)(blockIdx.x - N_DIM) * 256 + tid) * 2;
        float4 v0 = reinterpret_cast<const float4*>(x)[i];
        float4 v1 = reinterpret_cast<const float4*>(x)[i + 1];
        reinterpret_cast<uint2*>(g_Xh)[i]     = pack4_h(v0.x, v0.y, v0.z, v0.w);
        reinterpret_cast<uint2*>(g_Xh)[i + 1] = pack4_h(v1.x, v1.y, v1.z, v1.w);
        return;
    }

    const int row  = blockIdx.x;
    const int lane = tid & 31, warp = tid >> 5;

    const float4* wr = reinterpret_cast<const float4*>(w + (size_t)row * K_DIM);
    float4 v0 = wr[tid];
    float4 v1 = wr[tid + 256];

    float s = fabsf(v0.x)+fabsf(v0.y)+fabsf(v0.z)+fabsf(v0.w)
            + fabsf(v1.x)+fabsf(v1.y)+fabsf(v1.z)+fabsf(v1.w);
    #pragma unroll
    for (int o = 16; o > 0; o >>= 1) s += __shfl_xor_sync(0xffffffffu, s, o);

    __shared__ float red[8];
    __shared__ float sc_sh;
    if (lane == 0) red[warp] = s;
    __syncthreads();
    if (tid == 0) {
        float tot = 0.f;
        #pragma unroll
        for (int i = 0; i < 8; i++) tot += red[i];
        sc_sh = fmaxf(tot * (1.0f / (float)K_DIM), 1e-5f);
    }
    __syncthreads();
    const float sc = sc_sh;

    float q[8];
    q[0]=__fdiv_rn(v0.x,sc); q[1]=__fdiv_rn(v0.y,sc); q[2]=__fdiv_rn(v0.z,sc); q[3]=__fdiv_rn(v0.w,sc);
    q[4]=__fdiv_rn(v1.x,sc); q[5]=__fdiv_rn(v1.y,sc); q[6]=__fdiv_rn(v1.z,sc); q[7]=__fdiv_rn(v1.w,sc);
    #pragma unroll
    for (int i = 0; i < 8; i++) q[i] = fminf(fmaxf(rintf(q[i]), -1.f), 1.f);

    uint2* dst = reinterpret_cast<uint2*>(g_Wq + (size_t)row * K_DIM);
    dst[tid]       = pack4_h(q[0], q[1], q[2], q[3]);
    dst[tid + 256] = pack4_h(q[4], q[5], q[6], q[7]);

    if (tid == 0) g_scale[row] = sc;
}

// ---------------------------------------------------------------------------
// Kernel 2: fp16 HMMA GEMM.  C[m,n] = scale[n] * sum_k Xh[m,k]*Wq[n,k]
// 128x128x64 tile, 256 thr (8 warps 2x4, warp tile 64x32), 3-stage cp.async,
// 2 CTAs/SM, compile-time stage slots, A-fragment double-buffer across ks.
// ---------------------------------------------------------------------------
__global__ __launch_bounds__(NTHREADS, 2) void gemm_f16_kernel(float* __restrict__ C) {
    extern __shared__ char smem[];
    const uint32_t sbase = smem_u32(smem);

    const int tid  = threadIdx.x;
    const int lane = tid & 31;
    const int warp = tid >> 5;
    const int wrow = warp >> 2;           // 0..1 (M, 64 each)
    const int wcol = warp & 3;            // 0..3 (N, 32 each)

    // CTA swizzle: GROUP=8 along M, walk all N inside a group (L2 reuse)
    const int GRID_N = N_DIM / BN;        // 64
    const int GROUP  = 8;
    const int nig    = GROUP * GRID_N;    // 512
    const int bid    = blockIdx.x;
    const int bm     = (bid / nig) * GROUP + (bid % nig) % GROUP;
    const int bn     = (bid % nig) / GROUP;

    const __half* Ag = g_Xh + (size_t)(bm * BM) * K_DIM;
    const __half* Bg = g_Wq + (size_t)(bn * BN) * K_DIM;

    // ldmatrix per-lane row/seg decomposition
    const int a_row = (lane & 7) + ((lane >> 3) & 1) * 8;   // 0..15
    const int a_sh  = lane >> 4;                            // k-seg half 0/1
    const int b_row = (lane & 7) + (lane >> 4) * 8;         // 0..15
    const int b_sh  = (lane >> 3) & 1;
    const int lxor  = lane & 7;

    // Pre-load epilogue scales (hidden under the mainloop)
    const int n_sc = bn * BN + wcol * 32 + 2 * (lane & 3);
    float scv[8];
    #pragma unroll
    for (int nt = 0; nt < 4; nt++) {
        scv[2*nt]   = __ldg(g_scale + n_sc + nt * 8);
        scv[2*nt+1] = __ldg(g_scale + n_sc + nt * 8 + 1);
    }

    float acc[4][4][4];
    #pragma unroll
    for (int a = 0; a < 4; a++)
        #pragma unroll
        for (int b = 0; b < 4; b++)
            #pragma unroll
            for (int c = 0; c < 4; c++) acc[a][b][c] = 0.f;

    // --- stage loader: 8 x 16B per thread (A:4, B:4) ---
    auto load_stage = [&](int kt, uint32_t st) {
        const int kof = kt * BK;
        #pragma unroll
        for (int i = 0; i < 4; i++) {                 // A
            int flat = tid + NTHREADS * i;
            int row = flat >> 3, seg = flat & 7;
            cp16(st + row * 128 + ((seg ^ (row & 7)) << 4),
                 Ag + (size_t)row * K_DIM + kof + seg * 8);
        }
        #pragma unroll
        for (int i = 0; i < 4; i++) {                 // B
            int flat = tid + NTHREADS * i;
            int row = flat >> 3, seg = flat & 7;
            cp16(st + A_BYTES + row * 128 + ((seg ^ (row & 7)) << 4),
                 Bg + (size_t)row * K_DIM + kof + seg * 8);
        }
        asm volatile("cp.async.commit_group;\n" ::: "memory");
    };

    // A-fragment loader for one ks step
    auto load_a = [&](uint32_t aB, int ks, uint32_t (*af)[4]) {
        #pragma unroll
        for (int mt = 0; mt < 4; mt++) {
            const int row = wrow * 64 + mt * 16 + a_row;
            const int seg = 2 * ks + a_sh;
            ldsm_x4(af[mt][0], af[mt][1], af[mt][2], af[mt][3],
                    aB + row * 128 + ((seg ^ lxor) << 4));
        }
    };

    // one k-iteration with compile-time stage slots; A frags double-buffered
    auto iter = [&](int kt, uint32_t cslot, uint32_t lslot) {
        asm volatile("cp.async.wait_group %0;\n" :: "n"(NSTAGE - 2) : "memory");
        __syncthreads();
        const int j = kt + NSTAGE - 1;
        if (j < NKT) {
            load_stage(j, sbase + lslot * STAGE_BYTES);
        } else {
            asm volatile("cp.async.commit_group;\n" ::: "memory");
        }
        const uint32_t aB = sbase + cslot * STAGE_BYTES;
        const uint32_t bB = aB + A_BYTES;

        uint32_t af[2][4][4];
        load_a(aB, 0, af[0]);
        #pragma unroll
        for (int ks = 0; ks < 4; ks++) {
            if (ks < 3) load_a(aB, ks + 1, af[(ks + 1) & 1]);   // prefetch next A
            uint32_t bf[2][4];
            #pragma unroll
            for (int nt = 0; nt < 2; nt++) {
                const int row = wcol * 32 + nt * 16 + b_row;
                const int seg = 2 * ks + b_sh;
                ldsm_x4(bf[nt][0], bf[nt][1], bf[nt][2], bf[nt][3],
                        bB + row * 128 + ((seg ^ lxor) << 4));
            }
            uint32_t (*ac)[4] = af[ks & 1];
            #pragma unroll
            for (int mt = 0; mt < 4; mt++)
                #pragma unroll
                for (int nt = 0; nt < 2; nt++) {
                    asm volatile(
                        "mma.sync.aligned.m16n8k16.row.col.f32.f16.f16.f32 "
                        "{%0,%1,%2,%3}, {%4,%5,%6,%7}, {%8,%9}, {%0,%1,%2,%3};\n"
                        : "+f"(acc[mt][2*nt][0]), "+f"(acc[mt][2*nt][1]),
                          "+f"(acc[mt][2*nt][2]), "+f"(acc[mt][2*nt][3])
                        : "r"(ac[mt][0]), "r"(ac[mt][1]), "r"(ac[mt][2]), "r"(ac[mt][3]),
                          "r"(bf[nt][0]), "r"(bf[nt][1]));
                    asm volatile(
                        "mma.sync.aligned.m16n8k16.row.col.f32.f16.f16.f32 "
                        "{%0,%1,%2,%3}, {%4,%5,%6,%7}, {%8,%9}, {%0,%1,%2,%3};\n"
                        : "+f"(acc[mt][2*nt+1][0]), "+f"(acc[mt][2*nt+1][1]),
                          "+f"(acc[mt][2*nt+1][2]), "+f"(acc[mt][2*nt+1][3])
                        : "r"(ac[mt][0]), "r"(ac[mt][1]), "r"(ac[mt][2]), "r"(ac[mt][3]),
                          "r"(bf[nt][2]), "r"(bf[nt][3]));
                }
        }
    };

    // prologue: stages 0,1
    load_stage(0, sbase);
    load_stage(1, sbase + STAGE_BYTES);

    // main loop: 30 iterations unrolled by 3 (stage slots constant), + 2 tail
    #pragma unroll 1
    for (int kt = 0; kt < 30; kt += 3) {
        iter(kt + 0, 0, 2);
        iter(kt + 1, 1, 0);
        iter(kt + 2, 2, 1);
    }
    iter(30, 0, 2);
    iter(31, 1, 0);

    // ---- epilogue: per-column scale (pre-loaded), fp32 stores ----
    const int l4r = lane >> 2;            // 0..7
    #pragma unroll
    for (int mt = 0; mt < 4; mt++) {
        const int r0 = bm * BM + wrow * 64 + mt * 16 + l4r;
        #pragma unroll
        for (int nt = 0; nt < 4; nt++) {
            const int n0 = n_sc + nt * 8;
            float2 v0 = make_float2(acc[mt][nt][0] * scv[2*nt], acc[mt][nt][1] * scv[2*nt+1]);
            float2 v1 = make_float2(acc[mt][nt][2] * scv[2*nt], acc[mt][nt][3] * scv[2*nt+1]);
            *reinterpret_cast<float2*>(C + (size_t)r0 * N_DIM + n0)       = v0;
            *reinterpret_cast<float2*>(C + (size_t)(r0 + 8) * N_DIM + n0) = v1;
        }
    }
}

// ---------------------------------------------------------------------------
extern "C" void kernel_launch(void* const* d_in, const int* in_sizes, int n_in,
                              void* d_out, int out_size) {
    (void)in_sizes; (void)n_in; (void)out_size;
    const float* x = (const float*)d_in[0];
    const float* w = (const float*)d_in[1];
    float* out = (float*)d_out;

    // merged prep: 8192 W-row blocks + 8192 x-conversion blocks (8 floats/thr)
    prep_kernel<<<N_DIM + (unsigned)((size_t)M_DIM * K_DIM / 8 / 256), 256>>>(w, x);

    cudaFuncSetAttribute(gemm_f16_kernel,
                         cudaFuncAttributeMaxDynamicSharedMemorySize, SMEM_TOTAL);
    gemm_f16_kernel<<<(M_DIM / BM) * (N_DIM / BN), NTHREADS, SMEM_TOTAL>>>(out);
}